// round 10
// baseline (speedup 1.0000x reference)
#include <cuda_runtime.h>
#include <cuda_bf16.h>
#include <stdint.h>
#include <math.h>

#define TOTALP  200000
#define Nn      50000
#define CF      32
#define GRES    32
#define PRES    128
#define HID     256
#define NBLK    5

#define MT      64                   // points per CTA
#define THREADS 512                  // 16 warps: 2 warpM x 8 warpN
#define NBLOCKS (TOTALP / MT)        // 3125 exact

#define SF      136                  // feature smem row stride (bf16, K=128 + pad 8)
#define SN      264                  // net smem row stride (bf16, K=256 + pad 8)

// weight blob per-block layout (bytes): fragment-packed bf16 splits
#define L0S0 0
#define L0S1 65536
#define L1S0 131072
#define L1S1 262144
#define L2S0 393216
#define L2S1 524288
#define BLK_STRIDE 655360

__device__ __align__(16) unsigned char g_wblob[(size_t)NBLK * BLK_STRIDE];
__device__ float g_cum[(NBLK + 1) * HID];

// ---------------- low-level helpers ----------------
__device__ __forceinline__ uint32_t s2u(const void* p) {
    uint32_t a;
    asm("{ .reg .u64 t; cvta.to.shared.u64 t, %1; cvt.u32.u64 %0, t; }" : "=r"(a) : "l"(p));
    return a;
}
__device__ __forceinline__ void sts32(uint32_t a, uint32_t v) {
    asm volatile("st.shared.b32 [%0], %1;" :: "r"(a), "r"(v) : "memory");
}
__device__ __forceinline__ void sts16(uint32_t a, unsigned short v) {
    asm volatile("st.shared.u16 [%0], %1;" :: "r"(a), "h"(v) : "memory");
}
__device__ __forceinline__ void ldm_x4(uint32_t* r, uint32_t addr) {
    asm volatile("ldmatrix.sync.aligned.m8n8.x4.shared.b16 {%0,%1,%2,%3}, [%4];"
                 : "=r"(r[0]), "=r"(r[1]), "=r"(r[2]), "=r"(r[3]) : "r"(addr));
}
__device__ __forceinline__ void mma16816(float* d, const uint32_t* a, const uint32_t* b) {
    asm volatile(
        "mma.sync.aligned.m16n8k16.row.col.f32.bf16.bf16.f32 "
        "{%0,%1,%2,%3}, {%4,%5,%6,%7}, {%8,%9}, {%0,%1,%2,%3};"
        : "+f"(d[0]), "+f"(d[1]), "+f"(d[2]), "+f"(d[3])
        : "r"(a[0]), "r"(a[1]), "r"(a[2]), "r"(a[3]), "r"(b[0]), "r"(b[1]));
}
__device__ __forceinline__ uint32_t pack_bf16(float v0, float v1) {
    __nv_bfloat16 h0 = __float2bfloat16(v0), h1 = __float2bfloat16(v1);
    return (uint32_t)__bfloat16_as_ushort(h0) | ((uint32_t)__bfloat16_as_ushort(h1) << 16);
}
__device__ __forceinline__ uint32_t pack_bf16_lo(float v0, float v1) {
    __nv_bfloat16 h0 = __float2bfloat16(v0), h1 = __float2bfloat16(v1);
    __nv_bfloat16 l0 = __float2bfloat16(v0 - __bfloat162float(h0));
    __nv_bfloat16 l1 = __float2bfloat16(v1 - __bfloat162float(h1));
    return (uint32_t)__bfloat16_as_ushort(l0) | ((uint32_t)__bfloat16_as_ushort(l1) << 16);
}

// ---------------- prep kernel (unchanged layout) ----------------
__global__ void prep_kernel(const float* __restrict__ Wc, const float* __restrict__ W0,
                            const float* __restrict__ W1, const float* __restrict__ bp,
                            const float* __restrict__ bc, const float* __restrict__ b1) {
    const int total = NBLK * 640 * 256;
    for (int i = blockIdx.x * blockDim.x + threadIdx.x; i < total; i += gridDim.x * blockDim.x) {
        int blk = i / (640 * 256);
        int r   = i % (640 * 256);
        int k   = r / 256;
        int n   = r % 256;
        float w; size_t base; size_t lsz; int kl;
        if (k < 128)      { kl = k;       w = Wc[((size_t)blk * 128 + kl) * 256 + n]; base = (size_t)blk * BLK_STRIDE + L0S0; lsz = 65536; }
        else if (k < 384) { kl = k - 128; w = W0[((size_t)blk * 256 + kl) * 256 + n]; base = (size_t)blk * BLK_STRIDE + L1S0; lsz = 131072; }
        else              { kl = k - 384; w = W1[((size_t)blk * 256 + kl) * 256 + n]; base = (size_t)blk * BLK_STRIDE + L2S0; lsz = 131072; }
        __nv_bfloat16 h = __float2bfloat16(w);
        __nv_bfloat16 l = __float2bfloat16(w - __bfloat162float(h));
        int t = kl >> 4, kr = kl & 15;
        int j = n >> 3;
        int lane = ((n & 7) << 2) | ((kr & 7) >> 1);
        int reg = kr >> 3;
        size_t off = (size_t)((t * 32 + j) * 32 + lane) * 8 + reg * 4 + (kr & 1) * 2;
        *(unsigned short*)(g_wblob + base + off)       = __bfloat16_as_ushort(h);
        *(unsigned short*)(g_wblob + base + lsz + off) = __bfloat16_as_ushort(l);
    }
    if (blockIdx.x == 0 && threadIdx.x < 256) {
        int c = threadIdx.x;
        float pre = bp[c];
        for (int i = 0; i < NBLK; i++) {
            g_cum[i * 256 + c] = pre + bc[i * 256 + c];
            pre += bc[i * 256 + c] + b1[i * 256 + c];
        }
        g_cum[NBLK * 256 + c] = pre;
    }
}

// ---------------- shared memory ----------------
struct SMX {
    unsigned char feat0[MT * SF * 2];
    unsigned char feat1[MT * SF * 2];
    unsigned char na0[MT * SN * 2];
    unsigned char na1[MT * SN * 2];
    float px[MT], py[MT], pz[MT];
    int   bq[MT];
    int   gx0[MT], gy0[MT], gz0[MT];
    float gwx[MT], gwy[MT], gwz[MT];
    int   qx0[MT], qy0[MT], qz0[MT];
    float qwx[MT], qwy[MT], qwz[MT];
    float outp[MT][8];
};

__device__ __forceinline__ float bilin(const float* __restrict__ base,
                                       int ix, int iy, float wu, float wv) {
    int o = (iy << 7) + ix;
    float a = base[o], b = base[o + 1];
    float c = base[o + 128], d = base[o + 129];
    float t0 = a + (b - a) * wu;
    float t1 = c + (d - c) * wu;
    return t0 + (t1 - t0) * wv;
}

// 3-pass split GEMM: acc += A @ W ; warp tile 32 rows x 32 cols
template <int KT>
__device__ __forceinline__ void gemm3(float acc[2][4][4],
                                      uint32_t aS0, uint32_t aS1, int strideE,
                                      const unsigned char* __restrict__ g0,
                                      const unsigned char* __restrict__ g1,
                                      int wM, int wN, int lane) {
    const int rowB = strideE * 2;
    // ldmatrix per-lane address components
    const int grp  = lane >> 3;
    const int arow = (grp & 1) * 8 + (lane & 7);
    const int acolB = (grp >> 1) * 16;          // bytes: (g>>1)*8 elems
    const uint32_t abase0 = aS0 + (uint32_t)((wM * 32 + arow) * rowB) + acolB;
    const uint32_t abase1 = aS1 + (uint32_t)((wM * 32 + arow) * rowB) + acolB;

#pragma unroll 2
    for (int t = 0; t < KT; t++) {
        uint2 b0[4], b1[4];
        const uint2* p0 = reinterpret_cast<const uint2*>(g0) + ((t * 32 + wN * 4) * 32 + lane);
        const uint2* p1 = reinterpret_cast<const uint2*>(g1) + ((t * 32 + wN * 4) * 32 + lane);
#pragma unroll
        for (int nt = 0; nt < 4; nt++) { b0[nt] = __ldg(p0 + nt * 32); b1[nt] = __ldg(p1 + nt * 32); }

        uint32_t a0[2][4], a1[2][4];
#pragma unroll
        for (int mt = 0; mt < 2; mt++) {
            uint32_t off = (uint32_t)(mt * 16 * rowB + t * 32);    // t*16 elems = t*32 bytes
            ldm_x4(a0[mt], abase0 + off);
            ldm_x4(a1[mt], abase1 + off);
        }
#pragma unroll
        for (int mt = 0; mt < 2; mt++)
#pragma unroll
            for (int nt = 0; nt < 4; nt++) {
                mma16816(acc[mt][nt], a0[mt], (const uint32_t*)&b0[nt]);
                mma16816(acc[mt][nt], a1[mt], (const uint32_t*)&b0[nt]);
                mma16816(acc[mt][nt], a0[mt], (const uint32_t*)&b1[nt]);
            }
    }
}

// epilogue: relu(acc + bias) -> split bf16 into padded smem
__device__ __forceinline__ void epi_write(const float acc[2][4][4],
                                          const float* __restrict__ bias,
                                          uint32_t dst0, uint32_t dst1,
                                          int wM, int wN, int lane) {
    const int rowB = SN * 2;
#pragma unroll
    for (int mt = 0; mt < 2; mt++) {
        int Rb = wM * 32 + mt * 16 + (lane >> 2);
#pragma unroll
        for (int nt = 0; nt < 4; nt++) {
            int C = wN * 32 + nt * 8 + (lane & 3) * 2;
            float bb0 = __ldg(bias + C), bb1 = __ldg(bias + C + 1);
#pragma unroll
            for (int rh = 0; rh < 2; rh++) {
                float v0 = fmaxf(acc[mt][nt][rh * 2 + 0] + bb0, 0.0f);
                float v1 = fmaxf(acc[mt][nt][rh * 2 + 1] + bb1, 0.0f);
                uint32_t off = (uint32_t)((Rb + rh * 8) * rowB + C * 2);
                sts32(dst0 + off, pack_bf16(v0, v1));
                sts32(dst1 + off, pack_bf16_lo(v0, v1));
            }
        }
    }
}

__global__ void __launch_bounds__(THREADS, 1)
decoder_kernel(const float* __restrict__ p,
               const float* __restrict__ c_grid,
               const float* __restrict__ c_xy,
               const float* __restrict__ c_yz,
               const float* __restrict__ c_xz,
               const float* __restrict__ Wp,
               const float* __restrict__ b0g,
               const float* __restrict__ Wout,
               const float* __restrict__ bout,
               float* __restrict__ out) {
    extern __shared__ char smem_raw[];
    SMX& s = *reinterpret_cast<SMX*>(smem_raw);

    const int tid  = threadIdx.x;
    const int wid  = tid >> 5;
    const int lane = tid & 31;
    const int wM   = wid >> 3;      // 0..1
    const int wN   = wid & 7;       // 0..7
    const int q0   = blockIdx.x * MT;

    const uint32_t f0a = s2u(s.feat0), f1a = s2u(s.feat1);
    const uint32_t n0a = s2u(s.na0),   n1a = s2u(s.na1);

    // ---- coordinate prep ----
    if (tid < MT) {
        int q = q0 + tid;
        float x = p[q * 3 + 0], y = p[q * 3 + 1], z = p[q * 3 + 2];
        s.px[tid] = x; s.py[tid] = y; s.pz[tid] = z;
        s.bq[tid] = q / Nn;
        float xn = fminf(fmaxf(x / 1.101f + 0.5f, 0.0f), 1.0f - 1e-5f);
        float yn = fminf(fmaxf(y / 1.101f + 0.5f, 0.0f), 1.0f - 1e-5f);
        float zn = fminf(fmaxf(z / 1.101f + 0.5f, 0.0f), 1.0f - 1e-5f);
        float fgx = xn * (GRES - 1), fgy = yn * (GRES - 1), fgz = zn * (GRES - 1);
        int gx = (int)floorf(fgx), gy = (int)floorf(fgy), gz = (int)floorf(fgz);
        s.gx0[tid] = gx; s.gy0[tid] = gy; s.gz0[tid] = gz;
        s.gwx[tid] = fgx - gx; s.gwy[tid] = fgy - gy; s.gwz[tid] = fgz - gz;
        float fpx = xn * (PRES - 1), fpy = yn * (PRES - 1), fpz = zn * (PRES - 1);
        int px0 = (int)floorf(fpx), py0 = (int)floorf(fpy), pz0 = (int)floorf(fpz);
        s.qx0[tid] = px0; s.qy0[tid] = py0; s.qz0[tid] = pz0;
        s.qwx[tid] = fpx - px0; s.qwy[tid] = fpy - py0; s.qwz[tid] = fpz - pz0;
    }
    __syncthreads();

    // ---- features -> split bf16 feat buffers (padded row-major) ----
    for (int task = tid; task < MT * CF; task += THREADS) {
        int pp = task >> 5, ch = task & 31;
        int bc_ch = s.bq[pp] * CF + ch;
        float fv[4];
        {
            const float* g = c_grid + ((size_t)bc_ch << 15);
            int o = (s.gz0[pp] << 10) + (s.gy0[pp] << 5) + s.gx0[pp];
            float wx = s.gwx[pp], wy = s.gwy[pp], wz = s.gwz[pp];
            float v000 = g[o],        v001 = g[o + 1];
            float v010 = g[o + 32],   v011 = g[o + 33];
            float v100 = g[o + 1024], v101 = g[o + 1025];
            float v110 = g[o + 1056], v111 = g[o + 1057];
            float c00 = v000 + (v001 - v000) * wx;
            float c01 = v010 + (v011 - v010) * wx;
            float c10 = v100 + (v101 - v100) * wx;
            float c11 = v110 + (v111 - v110) * wx;
            float cz0 = c00 + (c01 - c00) * wy;
            float cz1 = c10 + (c11 - c10) * wy;
            fv[0] = cz0 + (cz1 - cz0) * wz;
        }
        {
            size_t poff = (size_t)bc_ch << 14;
            int x0 = s.qx0[pp], y0 = s.qy0[pp], z0 = s.qz0[pp];
            float wx = s.qwx[pp], wy = s.qwy[pp], wz = s.qwz[pp];
            fv[1] = bilin(c_xy + poff, x0, y0, wx, wy);
            fv[2] = bilin(c_yz + poff, y0, z0, wy, wz);
            fv[3] = bilin(c_xz + poff, x0, z0, wx, wz);
        }
#pragma unroll
        for (int fk = 0; fk < 4; fk++) {
            int k = fk * 32 + ch;
            __nv_bfloat16 h = __float2bfloat16(fv[fk]);
            __nv_bfloat16 l = __float2bfloat16(fv[fk] - __bfloat162float(h));
            uint32_t off = (uint32_t)((pp * SF + k) * 2);
            sts16(f0a + off, __bfloat16_as_ushort(h));
            sts16(f1a + off, __bfloat16_as_ushort(l));
        }
    }

    // ---- net acc init: netA = p @ Wp (biases folded into g_cum) ----
    float accN[2][4][4];
#pragma unroll
    for (int mt = 0; mt < 2; mt++) {
        int Rb = wM * 32 + mt * 16 + (lane >> 2);
#pragma unroll
        for (int nt = 0; nt < 4; nt++) {
            int C = wN * 32 + nt * 8 + (lane & 3) * 2;
            float w00 = __ldg(Wp + C),       w01 = __ldg(Wp + C + 1);
            float w10 = __ldg(Wp + 256 + C), w11 = __ldg(Wp + 256 + C + 1);
            float w20 = __ldg(Wp + 512 + C), w21 = __ldg(Wp + 512 + C + 1);
#pragma unroll
            for (int rh = 0; rh < 2; rh++) {
                int R = Rb + rh * 8;
                float x = s.px[R], y = s.py[R], z = s.pz[R];
                accN[mt][nt][rh * 2 + 0] = x * w00 + y * w10 + z * w20;
                accN[mt][nt][rh * 2 + 1] = x * w01 + y * w11 + z * w21;
            }
        }
    }
    __syncthreads();

    // ---- 5 residual blocks ----
    for (int blk = 0; blk < NBLK; blk++) {
        const unsigned char* bb = g_wblob + (size_t)blk * BLK_STRIDE;
        const float* cum = g_cum + blk * 256;
        const float* b0L = b0g + blk * 256;

        // (a) netA += c @ Wc
        gemm3<8>(accN, f0a, f1a, SF, bb + L0S0, bb + L0S1, wM, wN, lane);

        // (b) tmp = relu(netA + cum) @ W0
        __syncthreads();
        epi_write(accN, cum, n0a, n1a, wM, wN, lane);
        __syncthreads();
        float accT[2][4][4];
#pragma unroll
        for (int mt = 0; mt < 2; mt++)
#pragma unroll
            for (int nt = 0; nt < 4; nt++)
#pragma unroll
                for (int r4 = 0; r4 < 4; r4++) accT[mt][nt][r4] = 0.0f;
        gemm3<16>(accT, n0a, n1a, SN, bb + L1S0, bb + L1S1, wM, wN, lane);

        // (c) netA += relu(tmp + b0) @ W1
        __syncthreads();
        epi_write(accT, b0L, n0a, n1a, wM, wN, lane);
        __syncthreads();
        gemm3<16>(accN, n0a, n1a, SN, bb + L2S0, bb + L2S1, wM, wN, lane);
    }

    // ---- output: out = relu(netA + cumF) @ Wout + bout ----
    {
        const float* cumF = g_cum + NBLK * 256;
        float part[2][2] = {{0.f, 0.f}, {0.f, 0.f}};
#pragma unroll
        for (int mt = 0; mt < 2; mt++)
#pragma unroll
            for (int nt = 0; nt < 4; nt++) {
                int C = wN * 32 + nt * 8 + (lane & 3) * 2;
                float c0 = __ldg(cumF + C), c1 = __ldg(cumF + C + 1);
                float w0 = __ldg(Wout + C), w1 = __ldg(Wout + C + 1);
#pragma unroll
                for (int rh = 0; rh < 2; rh++) {
                    part[mt][rh] += fmaxf(accN[mt][nt][rh * 2 + 0] + c0, 0.0f) * w0
                                  + fmaxf(accN[mt][nt][rh * 2 + 1] + c1, 0.0f) * w1;
                }
            }
#pragma unroll
        for (int mt = 0; mt < 2; mt++)
#pragma unroll
            for (int rh = 0; rh < 2; rh++) {
                float v = part[mt][rh];
                v += __shfl_xor_sync(0xFFFFFFFFu, v, 1);
                v += __shfl_xor_sync(0xFFFFFFFFu, v, 2);
                if ((lane & 3) == 0) {
                    int R = wM * 32 + mt * 16 + (lane >> 2) + rh * 8;
                    s.outp[R][wN] = v;
                }
            }
        __syncthreads();
        if (tid < MT) {
            float v = __ldg(bout);
#pragma unroll
            for (int j = 0; j < 8; j++) v += s.outp[tid][j];
            out[q0 + tid] = v;
        }
    }
}

extern "C" void kernel_launch(void* const* d_in, const int* in_sizes, int n_in,
                              void* d_out, int out_size) {
    const float* p      = (const float*)d_in[0];
    const float* c_grid = (const float*)d_in[1];
    const float* c_xy   = (const float*)d_in[2];
    const float* c_yz   = (const float*)d_in[3];
    const float* c_xz   = (const float*)d_in[4];
    const float* Wp     = (const float*)d_in[5];
    const float* bp     = (const float*)d_in[6];
    const float* Wc     = (const float*)d_in[7];
    const float* bc     = (const float*)d_in[8];
    const float* W0     = (const float*)d_in[9];
    const float* b0     = (const float*)d_in[10];
    const float* W1     = (const float*)d_in[11];
    const float* b1     = (const float*)d_in[12];
    const float* Wout   = (const float*)d_in[13];
    const float* bout   = (const float*)d_in[14];
    float* out = (float*)d_out;

    int smem = (int)sizeof(SMX);
    cudaFuncSetAttribute(decoder_kernel,
                         cudaFuncAttributeMaxDynamicSharedMemorySize, smem);

    prep_kernel<<<256, 256>>>(Wc, W0, W1, bp, bc, b1);
    decoder_kernel<<<NBLOCKS, THREADS, smem>>>(
        p, c_grid, c_xy, c_yz, c_xz, Wp, b0, Wout, bout, out);
}

// round 11
// speedup vs baseline: 1.0005x; 1.0005x over previous
#include <cuda_runtime.h>
#include <cuda_bf16.h>
#include <stdint.h>
#include <math.h>

#define TOTALP  200000
#define Nn      50000
#define CF      32
#define GRES    32
#define PRES    128
#define HID     256
#define NBLK    5

#define MT      64                   // points per CTA
#define THREADS 512                  // 16 warps: 2 warpM x 8 warpN
#define NBLOCKS (TOTALP / MT)        // 3125 exact

#define SF      136                  // feature smem row stride (bf16, K=128 + pad 8)
#define SN      264                  // net smem row stride (bf16, K=256 + pad 8)

// weight blob per-block layout (bytes): fragment-packed bf16 splits
#define L0S0 0
#define L0S1 65536
#define L1S0 131072
#define L1S1 262144
#define L2S0 393216
#define L2S1 524288
#define BLK_STRIDE 655360

__device__ __align__(16) unsigned char g_wblob[(size_t)NBLK * BLK_STRIDE];
__device__ float g_cum[(NBLK + 1) * HID];

// ---------------- low-level helpers ----------------
__device__ __forceinline__ uint32_t s2u(const void* p) {
    uint32_t a;
    asm("{ .reg .u64 t; cvta.to.shared.u64 t, %1; cvt.u32.u64 %0, t; }" : "=r"(a) : "l"(p));
    return a;
}
__device__ __forceinline__ void sts32(uint32_t a, uint32_t v) {
    asm volatile("st.shared.b32 [%0], %1;" :: "r"(a), "r"(v) : "memory");
}
__device__ __forceinline__ void sts16(uint32_t a, unsigned short v) {
    asm volatile("st.shared.u16 [%0], %1;" :: "r"(a), "h"(v) : "memory");
}
__device__ __forceinline__ void ldm_x4(uint32_t* r, uint32_t addr) {
    asm volatile("ldmatrix.sync.aligned.m8n8.x4.shared.b16 {%0,%1,%2,%3}, [%4];"
                 : "=r"(r[0]), "=r"(r[1]), "=r"(r[2]), "=r"(r[3]) : "r"(addr));
}
__device__ __forceinline__ void mma16816(float* d, const uint32_t* a, const uint32_t* b) {
    asm volatile(
        "mma.sync.aligned.m16n8k16.row.col.f32.bf16.bf16.f32 "
        "{%0,%1,%2,%3}, {%4,%5,%6,%7}, {%8,%9}, {%0,%1,%2,%3};"
        : "+f"(d[0]), "+f"(d[1]), "+f"(d[2]), "+f"(d[3])
        : "r"(a[0]), "r"(a[1]), "r"(a[2]), "r"(a[3]), "r"(b[0]), "r"(b[1]));
}
__device__ __forceinline__ uint32_t pack_bf16(float v0, float v1) {
    __nv_bfloat16 h0 = __float2bfloat16(v0), h1 = __float2bfloat16(v1);
    return (uint32_t)__bfloat16_as_ushort(h0) | ((uint32_t)__bfloat16_as_ushort(h1) << 16);
}
__device__ __forceinline__ uint32_t pack_bf16_lo(float v0, float v1) {
    __nv_bfloat16 h0 = __float2bfloat16(v0), h1 = __float2bfloat16(v1);
    __nv_bfloat16 l0 = __float2bfloat16(v0 - __bfloat162float(h0));
    __nv_bfloat16 l1 = __float2bfloat16(v1 - __bfloat162float(h1));
    return (uint32_t)__bfloat16_as_ushort(l0) | ((uint32_t)__bfloat16_as_ushort(l1) << 16);
}

// ---------------- prep kernel (unchanged layout) ----------------
__global__ void prep_kernel(const float* __restrict__ Wc, const float* __restrict__ W0,
                            const float* __restrict__ W1, const float* __restrict__ bp,
                            const float* __restrict__ bc, const float* __restrict__ b1) {
    const int total = NBLK * 640 * 256;
    for (int i = blockIdx.x * blockDim.x + threadIdx.x; i < total; i += gridDim.x * blockDim.x) {
        int blk = i / (640 * 256);
        int r   = i % (640 * 256);
        int k   = r / 256;
        int n   = r % 256;
        float w; size_t base; size_t lsz; int kl;
        if (k < 128)      { kl = k;       w = Wc[((size_t)blk * 128 + kl) * 256 + n]; base = (size_t)blk * BLK_STRIDE + L0S0; lsz = 65536; }
        else if (k < 384) { kl = k - 128; w = W0[((size_t)blk * 256 + kl) * 256 + n]; base = (size_t)blk * BLK_STRIDE + L1S0; lsz = 131072; }
        else              { kl = k - 384; w = W1[((size_t)blk * 256 + kl) * 256 + n]; base = (size_t)blk * BLK_STRIDE + L2S0; lsz = 131072; }
        __nv_bfloat16 h = __float2bfloat16(w);
        __nv_bfloat16 l = __float2bfloat16(w - __bfloat162float(h));
        int t = kl >> 4, kr = kl & 15;
        int j = n >> 3;
        int lane = ((n & 7) << 2) | ((kr & 7) >> 1);
        int reg = kr >> 3;
        size_t off = (size_t)((t * 32 + j) * 32 + lane) * 8 + reg * 4 + (kr & 1) * 2;
        *(unsigned short*)(g_wblob + base + off)       = __bfloat16_as_ushort(h);
        *(unsigned short*)(g_wblob + base + lsz + off) = __bfloat16_as_ushort(l);
    }
    if (blockIdx.x == 0 && threadIdx.x < 256) {
        int c = threadIdx.x;
        float pre = bp[c];
        for (int i = 0; i < NBLK; i++) {
            g_cum[i * 256 + c] = pre + bc[i * 256 + c];
            pre += bc[i * 256 + c] + b1[i * 256 + c];
        }
        g_cum[NBLK * 256 + c] = pre;
    }
}

// ---------------- shared memory ----------------
struct SMX {
    unsigned char feat0[MT * SF * 2];
    unsigned char feat1[MT * SF * 2];
    unsigned char na0[MT * SN * 2];
    unsigned char na1[MT * SN * 2];
    float px[MT], py[MT], pz[MT];
    int   bq[MT];
    int   gx0[MT], gy0[MT], gz0[MT];
    float gwx[MT], gwy[MT], gwz[MT];
    int   qx0[MT], qy0[MT], qz0[MT];
    float qwx[MT], qwy[MT], qwz[MT];
    float outp[MT][8];
};

__device__ __forceinline__ float bilin(const float* __restrict__ base,
                                       int ix, int iy, float wu, float wv) {
    int o = (iy << 7) + ix;
    float a = base[o], b = base[o + 1];
    float c = base[o + 128], d = base[o + 129];
    float t0 = a + (b - a) * wu;
    float t1 = c + (d - c) * wu;
    return t0 + (t1 - t0) * wv;
}

// 3-pass split GEMM: acc += A @ W ; warp tile 32 rows x 32 cols
// Pass-major mma ordering: same-accumulator RAW distance = 8 (was 1).
template <int KT>
__device__ __forceinline__ void gemm3(float acc[2][4][4],
                                      uint32_t aS0, uint32_t aS1, int strideE,
                                      const unsigned char* __restrict__ g0,
                                      const unsigned char* __restrict__ g1,
                                      int wM, int wN, int lane) {
    const int rowB = strideE * 2;
    const int grp  = lane >> 3;
    const int arow = (grp & 1) * 8 + (lane & 7);
    const int acolB = (grp >> 1) * 16;
    const uint32_t abase0 = aS0 + (uint32_t)((wM * 32 + arow) * rowB) + acolB;
    const uint32_t abase1 = aS1 + (uint32_t)((wM * 32 + arow) * rowB) + acolB;

#pragma unroll 2
    for (int t = 0; t < KT; t++) {
        uint2 b0[4], b1[4];
        const uint2* p0 = reinterpret_cast<const uint2*>(g0) + ((t * 32 + wN * 4) * 32 + lane);
        const uint2* p1 = reinterpret_cast<const uint2*>(g1) + ((t * 32 + wN * 4) * 32 + lane);
#pragma unroll
        for (int nt = 0; nt < 4; nt++) { b0[nt] = __ldg(p0 + nt * 32); b1[nt] = __ldg(p1 + nt * 32); }

        uint32_t a0[2][4], a1[2][4];
#pragma unroll
        for (int mt = 0; mt < 2; mt++) {
            uint32_t off = (uint32_t)(mt * 16 * rowB + t * 32);
            ldm_x4(a0[mt], abase0 + off);
            ldm_x4(a1[mt], abase1 + off);
        }
        // pass 1: a0 * b0  (8 independent accs)
#pragma unroll
        for (int mt = 0; mt < 2; mt++)
#pragma unroll
            for (int nt = 0; nt < 4; nt++)
                mma16816(acc[mt][nt], a0[mt], (const uint32_t*)&b0[nt]);
        // pass 2: a1 * b0
#pragma unroll
        for (int mt = 0; mt < 2; mt++)
#pragma unroll
            for (int nt = 0; nt < 4; nt++)
                mma16816(acc[mt][nt], a1[mt], (const uint32_t*)&b0[nt]);
        // pass 3: a0 * b1
#pragma unroll
        for (int mt = 0; mt < 2; mt++)
#pragma unroll
            for (int nt = 0; nt < 4; nt++)
                mma16816(acc[mt][nt], a0[mt], (const uint32_t*)&b1[nt]);
    }
}

// epilogue: relu(acc + bias) -> split bf16 into padded smem
__device__ __forceinline__ void epi_write(const float acc[2][4][4],
                                          const float* __restrict__ bias,
                                          uint32_t dst0, uint32_t dst1,
                                          int wM, int wN, int lane) {
    const int rowB = SN * 2;
#pragma unroll
    for (int mt = 0; mt < 2; mt++) {
        int Rb = wM * 32 + mt * 16 + (lane >> 2);
#pragma unroll
        for (int nt = 0; nt < 4; nt++) {
            int C = wN * 32 + nt * 8 + (lane & 3) * 2;
            float bb0 = __ldg(bias + C), bb1 = __ldg(bias + C + 1);
#pragma unroll
            for (int rh = 0; rh < 2; rh++) {
                float v0 = fmaxf(acc[mt][nt][rh * 2 + 0] + bb0, 0.0f);
                float v1 = fmaxf(acc[mt][nt][rh * 2 + 1] + bb1, 0.0f);
                uint32_t off = (uint32_t)((Rb + rh * 8) * rowB + C * 2);
                sts32(dst0 + off, pack_bf16(v0, v1));
                sts32(dst1 + off, pack_bf16_lo(v0, v1));
            }
        }
    }
}

__global__ void __launch_bounds__(THREADS, 1)
decoder_kernel(const float* __restrict__ p,
               const float* __restrict__ c_grid,
               const float* __restrict__ c_xy,
               const float* __restrict__ c_yz,
               const float* __restrict__ c_xz,
               const float* __restrict__ Wp,
               const float* __restrict__ b0g,
               const float* __restrict__ Wout,
               const float* __restrict__ bout,
               float* __restrict__ out) {
    extern __shared__ char smem_raw[];
    SMX& s = *reinterpret_cast<SMX*>(smem_raw);

    const int tid  = threadIdx.x;
    const int wid  = tid >> 5;
    const int lane = tid & 31;
    const int wM   = wid >> 3;      // 0..1
    const int wN   = wid & 7;       // 0..7
    const int q0   = blockIdx.x * MT;

    const uint32_t f0a = s2u(s.feat0), f1a = s2u(s.feat1);
    const uint32_t n0a = s2u(s.na0),   n1a = s2u(s.na1);

    // ---- coordinate prep ----
    if (tid < MT) {
        int q = q0 + tid;
        float x = p[q * 3 + 0], y = p[q * 3 + 1], z = p[q * 3 + 2];
        s.px[tid] = x; s.py[tid] = y; s.pz[tid] = z;
        s.bq[tid] = q / Nn;
        float xn = fminf(fmaxf(x / 1.101f + 0.5f, 0.0f), 1.0f - 1e-5f);
        float yn = fminf(fmaxf(y / 1.101f + 0.5f, 0.0f), 1.0f - 1e-5f);
        float zn = fminf(fmaxf(z / 1.101f + 0.5f, 0.0f), 1.0f - 1e-5f);
        float fgx = xn * (GRES - 1), fgy = yn * (GRES - 1), fgz = zn * (GRES - 1);
        int gx = (int)floorf(fgx), gy = (int)floorf(fgy), gz = (int)floorf(fgz);
        s.gx0[tid] = gx; s.gy0[tid] = gy; s.gz0[tid] = gz;
        s.gwx[tid] = fgx - gx; s.gwy[tid] = fgy - gy; s.gwz[tid] = fgz - gz;
        float fpx = xn * (PRES - 1), fpy = yn * (PRES - 1), fpz = zn * (PRES - 1);
        int px0 = (int)floorf(fpx), py0 = (int)floorf(fpy), pz0 = (int)floorf(fpz);
        s.qx0[tid] = px0; s.qy0[tid] = py0; s.qz0[tid] = pz0;
        s.qwx[tid] = fpx - px0; s.qwy[tid] = fpy - py0; s.qwz[tid] = fpz - pz0;
    }
    __syncthreads();

    // ---- features -> split bf16 feat buffers (padded row-major) ----
    for (int task = tid; task < MT * CF; task += THREADS) {
        int pp = task >> 5, ch = task & 31;
        int bc_ch = s.bq[pp] * CF + ch;
        float fv[4];
        {
            const float* g = c_grid + ((size_t)bc_ch << 15);
            int o = (s.gz0[pp] << 10) + (s.gy0[pp] << 5) + s.gx0[pp];
            float wx = s.gwx[pp], wy = s.gwy[pp], wz = s.gwz[pp];
            float v000 = g[o],        v001 = g[o + 1];
            float v010 = g[o + 32],   v011 = g[o + 33];
            float v100 = g[o + 1024], v101 = g[o + 1025];
            float v110 = g[o + 1056], v111 = g[o + 1057];
            float c00 = v000 + (v001 - v000) * wx;
            float c01 = v010 + (v011 - v010) * wx;
            float c10 = v100 + (v101 - v100) * wx;
            float c11 = v110 + (v111 - v110) * wx;
            float cz0 = c00 + (c01 - c00) * wy;
            float cz1 = c10 + (c11 - c10) * wy;
            fv[0] = cz0 + (cz1 - cz0) * wz;
        }
        {
            size_t poff = (size_t)bc_ch << 14;
            int x0 = s.qx0[pp], y0 = s.qy0[pp], z0 = s.qz0[pp];
            float wx = s.qwx[pp], wy = s.qwy[pp], wz = s.qwz[pp];
            fv[1] = bilin(c_xy + poff, x0, y0, wx, wy);
            fv[2] = bilin(c_yz + poff, y0, z0, wy, wz);
            fv[3] = bilin(c_xz + poff, x0, z0, wx, wz);
        }
#pragma unroll
        for (int fk = 0; fk < 4; fk++) {
            int k = fk * 32 + ch;
            __nv_bfloat16 h = __float2bfloat16(fv[fk]);
            __nv_bfloat16 l = __float2bfloat16(fv[fk] - __bfloat162float(h));
            uint32_t off = (uint32_t)((pp * SF + k) * 2);
            sts16(f0a + off, __bfloat16_as_ushort(h));
            sts16(f1a + off, __bfloat16_as_ushort(l));
        }
    }

    // ---- net acc init: netA = p @ Wp (biases folded into g_cum) ----
    float accN[2][4][4];
#pragma unroll
    for (int mt = 0; mt < 2; mt++) {
        int Rb = wM * 32 + mt * 16 + (lane >> 2);
#pragma unroll
        for (int nt = 0; nt < 4; nt++) {
            int C = wN * 32 + nt * 8 + (lane & 3) * 2;
            float w00 = __ldg(Wp + C),       w01 = __ldg(Wp + C + 1);
            float w10 = __ldg(Wp + 256 + C), w11 = __ldg(Wp + 256 + C + 1);
            float w20 = __ldg(Wp + 512 + C), w21 = __ldg(Wp + 512 + C + 1);
#pragma unroll
            for (int rh = 0; rh < 2; rh++) {
                int R = Rb + rh * 8;
                float x = s.px[R], y = s.py[R], z = s.pz[R];
                accN[mt][nt][rh * 2 + 0] = x * w00 + y * w10 + z * w20;
                accN[mt][nt][rh * 2 + 1] = x * w01 + y * w11 + z * w21;
            }
        }
    }
    __syncthreads();

    // ---- 5 residual blocks ----
    for (int blk = 0; blk < NBLK; blk++) {
        const unsigned char* bb = g_wblob + (size_t)blk * BLK_STRIDE;
        const float* cum = g_cum + blk * 256;
        const float* b0L = b0g + blk * 256;

        // (a) netA += c @ Wc
        gemm3<8>(accN, f0a, f1a, SF, bb + L0S0, bb + L0S1, wM, wN, lane);

        // (b) tmp = relu(netA + cum) @ W0
        __syncthreads();
        epi_write(accN, cum, n0a, n1a, wM, wN, lane);
        __syncthreads();
        float accT[2][4][4];
#pragma unroll
        for (int mt = 0; mt < 2; mt++)
#pragma unroll
            for (int nt = 0; nt < 4; nt++)
#pragma unroll
                for (int r4 = 0; r4 < 4; r4++) accT[mt][nt][r4] = 0.0f;
        gemm3<16>(accT, n0a, n1a, SN, bb + L1S0, bb + L1S1, wM, wN, lane);

        // (c) netA += relu(tmp + b0) @ W1
        __syncthreads();
        epi_write(accT, b0L, n0a, n1a, wM, wN, lane);
        __syncthreads();
        gemm3<16>(accN, n0a, n1a, SN, bb + L2S0, bb + L2S1, wM, wN, lane);
    }

    // ---- output: out = relu(netA + cumF) @ Wout + bout ----
    {
        const float* cumF = g_cum + NBLK * 256;
        float part[2][2] = {{0.f, 0.f}, {0.f, 0.f}};
#pragma unroll
        for (int mt = 0; mt < 2; mt++)
#pragma unroll
            for (int nt = 0; nt < 4; nt++) {
                int C = wN * 32 + nt * 8 + (lane & 3) * 2;
                float c0 = __ldg(cumF + C), c1 = __ldg(cumF + C + 1);
                float w0 = __ldg(Wout + C), w1 = __ldg(Wout + C + 1);
#pragma unroll
                for (int rh = 0; rh < 2; rh++) {
                    part[mt][rh] += fmaxf(accN[mt][nt][rh * 2 + 0] + c0, 0.0f) * w0
                                  + fmaxf(accN[mt][nt][rh * 2 + 1] + c1, 0.0f) * w1;
                }
            }
#pragma unroll
        for (int mt = 0; mt < 2; mt++)
#pragma unroll
            for (int rh = 0; rh < 2; rh++) {
                float v = part[mt][rh];
                v += __shfl_xor_sync(0xFFFFFFFFu, v, 1);
                v += __shfl_xor_sync(0xFFFFFFFFu, v, 2);
                if ((lane & 3) == 0) {
                    int R = wM * 32 + mt * 16 + (lane >> 2) + rh * 8;
                    s.outp[R][wN] = v;
                }
            }
        __syncthreads();
        if (tid < MT) {
            float v = __ldg(bout);
#pragma unroll
            for (int j = 0; j < 8; j++) v += s.outp[tid][j];
            out[q0 + tid] = v;
        }
    }
}

extern "C" void kernel_launch(void* const* d_in, const int* in_sizes, int n_in,
                              void* d_out, int out_size) {
    const float* p      = (const float*)d_in[0];
    const float* c_grid = (const float*)d_in[1];
    const float* c_xy   = (const float*)d_in[2];
    const float* c_yz   = (const float*)d_in[3];
    const float* c_xz   = (const float*)d_in[4];
    const float* Wp     = (const float*)d_in[5];
    const float* bp     = (const float*)d_in[6];
    const float* Wc     = (const float*)d_in[7];
    const float* bc     = (const float*)d_in[8];
    const float* W0     = (const float*)d_in[9];
    const float* b0     = (const float*)d_in[10];
    const float* W1     = (const float*)d_in[11];
    const float* b1     = (const float*)d_in[12];
    const float* Wout   = (const float*)d_in[13];
    const float* bout   = (const float*)d_in[14];
    float* out = (float*)d_out;

    int smem = (int)sizeof(SMX);
    cudaFuncSetAttribute(decoder_kernel,
                         cudaFuncAttributeMaxDynamicSharedMemorySize, smem);

    prep_kernel<<<256, 256>>>(Wc, W0, W1, bp, bc, b1);
    decoder_kernel<<<NBLOCKS, THREADS, smem>>>(
        p, c_grid, c_xy, c_yz, c_xz, Wp, b0, Wout, bout, out);
}

// round 14
// speedup vs baseline: 1.4838x; 1.4831x over previous
#include <cuda_runtime.h>
#include <cuda_bf16.h>
#include <stdint.h>
#include <math.h>

#define TOTALP  200000
#define Nn      50000
#define CF      32
#define GRES    32
#define PRES    128
#define HID     256
#define NBLK    5

#define MT      64                   // points per CTA
#define THREADS 256                  // 8 warps: 2 warpM x 4 warpN (warp tile 32x64)
#define NBLOCKS (TOTALP / MT)        // 3125 exact

#define SFW     132                  // feature smem row stride (floats, 128 + 4)  (132%32==4 -> conflict-free)
#define SNW     260                  // net smem row stride (floats, 256 + 4)      (260%32==4)

// tf32 weight blob per-block layout (bytes): fragment-packed b32
#define L0OFF 0                      // Wc  (K=128: 8 ktiles * 32 jtiles * 512B = 131072)
#define L1OFF 131072                 // W0  (K=256: 262144)
#define L2OFF 393216                 // W1  (K=256: 262144)
#define BLK_STRIDE 655360

__device__ __align__(16) unsigned char g_wblob[(size_t)NBLK * BLK_STRIDE];
__device__ float g_cum[(NBLK + 1) * HID];

// ---------------- low-level helpers ----------------
__device__ __forceinline__ uint32_t s2u(const void* p) {
    uint32_t a;
    asm("{ .reg .u64 t; cvta.to.shared.u64 t, %1; cvt.u32.u64 %0, t; }" : "=r"(a) : "l"(p));
    return a;
}
__device__ __forceinline__ uint32_t lds32(uint32_t a) {
    uint32_t v;
    asm volatile("ld.shared.b32 %0, [%1];" : "=r"(v) : "r"(a));
    return v;
}
__device__ __forceinline__ void sts64(uint32_t a, uint32_t v0, uint32_t v1) {
    asm volatile("st.shared.v2.b32 [%0], {%1, %2};" :: "r"(a), "r"(v0), "r"(v1) : "memory");
}
__device__ __forceinline__ void sts32(uint32_t a, uint32_t v) {
    asm volatile("st.shared.b32 [%0], %1;" :: "r"(a), "r"(v) : "memory");
}
__device__ __forceinline__ uint32_t f2tf32(float f) {
    uint32_t r;
    asm("cvt.rna.tf32.f32 %0, %1;" : "=r"(r) : "f"(f));
    return r;
}
__device__ __forceinline__ void mma_tf32(float* d, uint32_t a0, uint32_t a1,
                                         uint32_t a2, uint32_t a3,
                                         uint32_t b0, uint32_t b1) {
    asm volatile(
        "mma.sync.aligned.m16n8k8.row.col.f32.tf32.tf32.f32 "
        "{%0,%1,%2,%3}, {%4,%5,%6,%7}, {%8,%9}, {%0,%1,%2,%3};"
        : "+f"(d[0]), "+f"(d[1]), "+f"(d[2]), "+f"(d[3])
        : "r"(a0), "r"(a1), "r"(a2), "r"(a3), "r"(b0), "r"(b1));
}

// ---------------- prep kernel: tf32-convert + fragment-pack weights ----------------
// Consumer lane l of (ktile t, jtile j) does one LDG.128 at ((t*32+j)*32+l)*16:
//   comp 0..3 = W[k0+{0,4,8,12}+(l&3)][j*8+(l>>2)]  (k0 = t*16)
__global__ void prep_kernel(const float* __restrict__ Wc, const float* __restrict__ W0,
                            const float* __restrict__ W1, const float* __restrict__ bp,
                            const float* __restrict__ bc, const float* __restrict__ b1) {
    const int total = NBLK * 640 * 256;
    for (int i = blockIdx.x * blockDim.x + threadIdx.x; i < total; i += gridDim.x * blockDim.x) {
        int blk = i / (640 * 256);
        int r   = i % (640 * 256);
        int k   = r / 256;
        int n   = r % 256;
        float w; size_t base; int kl;
        if (k < 128)      { kl = k;       w = Wc[((size_t)blk * 128 + kl) * 256 + n]; base = (size_t)blk * BLK_STRIDE + L0OFF; }
        else if (k < 384) { kl = k - 128; w = W0[((size_t)blk * 256 + kl) * 256 + n]; base = (size_t)blk * BLK_STRIDE + L1OFF; }
        else              { kl = k - 384; w = W1[((size_t)blk * 256 + kl) * 256 + n]; base = (size_t)blk * BLK_STRIDE + L2OFF; }
        int t = kl >> 4, kr = kl & 15;
        int j = n >> 3;
        int lane = ((n & 7) << 2) | (kr & 3);
        int comp = kr >> 2;
        size_t off = base + (size_t)(((t * 32 + j) * 32 + lane) * 16 + comp * 4);
        uint32_t tf;
        asm("cvt.rna.tf32.f32 %0, %1;" : "=r"(tf) : "f"(w));
        *(uint32_t*)(g_wblob + off) = tf;
    }
    if (blockIdx.x == 0 && threadIdx.x < 256) {
        int c = threadIdx.x;
        float pre = bp[c];
        for (int i = 0; i < NBLK; i++) {
            g_cum[i * 256 + c] = pre + bc[i * 256 + c];
            pre += bc[i * 256 + c] + b1[i * 256 + c];
        }
        g_cum[NBLK * 256 + c] = pre;
    }
}

// ---------------- shared memory ----------------
struct SMX {
    float feat[MT * SFW];       // 33792 B, tf32-rounded activations (K=128)
    float na[MT * SNW];         // 66560 B, tf32-rounded activations (K=256)
    float px[MT], py[MT], pz[MT];
    int   bq[MT];
    int   gx0[MT], gy0[MT], gz0[MT];
    float gwx[MT], gwy[MT], gwz[MT];
    int   qx0[MT], qy0[MT], qz0[MT];
    float qwx[MT], qwy[MT], qwz[MT];
    float outp[MT][4];
};

__device__ __forceinline__ float bilin(const float* __restrict__ base,
                                       int ix, int iy, float wu, float wv) {
    int o = (iy << 7) + ix;
    float a = base[o], b = base[o + 1];
    float c = base[o + 128], d = base[o + 129];
    float t0 = a + (b - a) * wu;
    float t1 = c + (d - c) * wu;
    return t0 + (t1 - t0) * wv;
}

// single-pass tf32 GEMM: acc += A @ W ; warp tile 32 rows x 64 cols.
// B double-buffered in registers to break the load/mma convoy.
template <int KT>
__device__ __forceinline__ void gemm_tf32(float acc[2][8][4],
                                          uint32_t aS, int strideE,
                                          const uint4* __restrict__ gB,
                                          int wM, int wN, int lane) {
    const int r = lane >> 2, c = lane & 3;
    const uint32_t aR0 = aS + (uint32_t)((wM * 32 + r) * strideE + c) * 4u;
    const uint4* __restrict__ pB = gB + wN * 8 * 32 + lane;

    uint4 bb[2][8];
#pragma unroll
    for (int nt = 0; nt < 8; nt++) bb[0][nt] = __ldg(pB + nt * 32);

#pragma unroll
    for (int t = 0; t < KT; t++) {
        const int cur = t & 1;
        if (t + 1 < KT) {
#pragma unroll
            for (int nt = 0; nt < 8; nt++)
                bb[cur ^ 1][nt] = __ldg(pB + (t + 1) * 1024 + nt * 32);
        }
        uint32_t av[2][8];
#pragma unroll
        for (int mt = 0; mt < 2; mt++) {
            uint32_t a0 = aR0 + (uint32_t)(mt * 16 * strideE + t * 16) * 4u;
            uint32_t a8 = a0 + (uint32_t)(8 * strideE) * 4u;
            av[mt][0] = lds32(a0);       av[mt][1] = lds32(a8);
            av[mt][2] = lds32(a0 + 16);  av[mt][3] = lds32(a8 + 16);
            av[mt][4] = lds32(a0 + 32);  av[mt][5] = lds32(a8 + 32);
            av[mt][6] = lds32(a0 + 48);  av[mt][7] = lds32(a8 + 48);
        }
        // instr0 over all 16 accs (k0..k0+7), then instr1 (k0+8..k0+15)
#pragma unroll
        for (int mt = 0; mt < 2; mt++)
#pragma unroll
            for (int nt = 0; nt < 8; nt++)
                mma_tf32(acc[mt][nt], av[mt][0], av[mt][1], av[mt][2], av[mt][3],
                         bb[cur][nt].x, bb[cur][nt].y);
#pragma unroll
        for (int mt = 0; mt < 2; mt++)
#pragma unroll
            for (int nt = 0; nt < 8; nt++)
                mma_tf32(acc[mt][nt], av[mt][4], av[mt][5], av[mt][6], av[mt][7],
                         bb[cur][nt].z, bb[cur][nt].w);
    }
}

// epilogue: relu(acc + bias) -> tf32-rounded fp32 into na smem
__device__ __forceinline__ void epi_write(const float acc[2][8][4],
                                          const float* __restrict__ bias,
                                          uint32_t dst,
                                          int wM, int wN, int lane) {
#pragma unroll
    for (int mt = 0; mt < 2; mt++) {
        int Rb = wM * 32 + mt * 16 + (lane >> 2);
#pragma unroll
        for (int nt = 0; nt < 8; nt++) {
            int C = wN * 64 + nt * 8 + (lane & 3) * 2;
            float bb0 = __ldg(bias + C), bb1 = __ldg(bias + C + 1);
#pragma unroll
            for (int rh = 0; rh < 2; rh++) {
                float v0 = fmaxf(acc[mt][nt][rh * 2 + 0] + bb0, 0.0f);
                float v1 = fmaxf(acc[mt][nt][rh * 2 + 1] + bb1, 0.0f);
                uint32_t off = dst + (uint32_t)((Rb + rh * 8) * SNW + C) * 4u;
                sts64(off, f2tf32(v0), f2tf32(v1));
            }
        }
    }
}

__global__ void __launch_bounds__(THREADS, 1)
decoder_kernel(const float* __restrict__ p,
               const float* __restrict__ c_grid,
               const float* __restrict__ c_xy,
               const float* __restrict__ c_yz,
               const float* __restrict__ c_xz,
               const float* __restrict__ Wp,
               const float* __restrict__ b0g,
               const float* __restrict__ Wout,
               const float* __restrict__ bout,
               float* __restrict__ out) {
    extern __shared__ char smem_raw[];
    SMX& s = *reinterpret_cast<SMX*>(smem_raw);

    const int tid  = threadIdx.x;
    const int wid  = tid >> 5;
    const int lane = tid & 31;
    const int wM   = wid >> 2;      // 0..1
    const int wN   = wid & 3;       // 0..3
    const int q0   = blockIdx.x * MT;

    const uint32_t fa = s2u(s.feat);
    const uint32_t na = s2u(s.na);

    // ---- coordinate prep ----
    if (tid < MT) {
        int q = q0 + tid;
        float x = p[q * 3 + 0], y = p[q * 3 + 1], z = p[q * 3 + 2];
        s.px[tid] = x; s.py[tid] = y; s.pz[tid] = z;
        s.bq[tid] = q / Nn;
        float xn = fminf(fmaxf(x / 1.101f + 0.5f, 0.0f), 1.0f - 1e-5f);
        float yn = fminf(fmaxf(y / 1.101f + 0.5f, 0.0f), 1.0f - 1e-5f);
        float zn = fminf(fmaxf(z / 1.101f + 0.5f, 0.0f), 1.0f - 1e-5f);
        float fgx = xn * (GRES - 1), fgy = yn * (GRES - 1), fgz = zn * (GRES - 1);
        int gx = (int)floorf(fgx), gy = (int)floorf(fgy), gz = (int)floorf(fgz);
        s.gx0[tid] = gx; s.gy0[tid] = gy; s.gz0[tid] = gz;
        s.gwx[tid] = fgx - gx; s.gwy[tid] = fgy - gy; s.gwz[tid] = fgz - gz;
        float fpx = xn * (PRES - 1), fpy = yn * (PRES - 1), fpz = zn * (PRES - 1);
        int px0 = (int)floorf(fpx), py0 = (int)floorf(fpy), pz0 = (int)floorf(fpz);
        s.qx0[tid] = px0; s.qy0[tid] = py0; s.qz0[tid] = pz0;
        s.qwx[tid] = fpx - px0; s.qwy[tid] = fpy - py0; s.qwz[tid] = fpz - pz0;
    }
    __syncthreads();

    // ---- features -> tf32-rounded fp32 feat buffer ----
    for (int task = tid; task < MT * CF; task += THREADS) {
        int pp = task >> 5, ch = task & 31;
        int bc_ch = s.bq[pp] * CF + ch;
        float fv[4];
        {
            const float* g = c_grid + ((size_t)bc_ch << 15);
            int o = (s.gz0[pp] << 10) + (s.gy0[pp] << 5) + s.gx0[pp];
            float wx = s.gwx[pp], wy = s.gwy[pp], wz = s.gwz[pp];
            float v000 = g[o],        v001 = g[o + 1];
            float v010 = g[o + 32],   v011 = g[o + 33];
            float v100 = g[o + 1024], v101 = g[o + 1025];
            float v110 = g[o + 1056], v111 = g[o + 1057];
            float c00 = v000 + (v001 - v000) * wx;
            float c01 = v010 + (v011 - v010) * wx;
            float c10 = v100 + (v101 - v100) * wx;
            float c11 = v110 + (v111 - v110) * wx;
            float cz0 = c00 + (c01 - c00) * wy;
            float cz1 = c10 + (c11 - c10) * wy;
            fv[0] = cz0 + (cz1 - cz0) * wz;
        }
        {
            size_t poff = (size_t)bc_ch << 14;
            int x0 = s.qx0[pp], y0 = s.qy0[pp], z0 = s.qz0[pp];
            float wx = s.qwx[pp], wy = s.qwy[pp], wz = s.qwz[pp];
            fv[1] = bilin(c_xy + poff, x0, y0, wx, wy);
            fv[2] = bilin(c_yz + poff, y0, z0, wy, wz);
            fv[3] = bilin(c_xz + poff, x0, z0, wx, wz);
        }
#pragma unroll
        for (int fk = 0; fk < 4; fk++) {
            int k = fk * 32 + ch;
            sts32(fa + (uint32_t)(pp * SFW + k) * 4u, f2tf32(fv[fk]));
        }
    }

    // ---- net acc init: netA = p @ Wp (biases folded into g_cum) ----
    float accN[2][8][4];
#pragma unroll
    for (int mt = 0; mt < 2; mt++) {
        int Rb = wM * 32 + mt * 16 + (lane >> 2);
#pragma unroll
        for (int nt = 0; nt < 8; nt++) {
            int C = wN * 64 + nt * 8 + (lane & 3) * 2;
            float w00 = __ldg(Wp + C),       w01 = __ldg(Wp + C + 1);
            float w10 = __ldg(Wp + 256 + C), w11 = __ldg(Wp + 256 + C + 1);
            float w20 = __ldg(Wp + 512 + C), w21 = __ldg(Wp + 512 + C + 1);
#pragma unroll
            for (int rh = 0; rh < 2; rh++) {
                int R = Rb + rh * 8;
                float x = s.px[R], y = s.py[R], z = s.pz[R];
                accN[mt][nt][rh * 2 + 0] = x * w00 + y * w10 + z * w20;
                accN[mt][nt][rh * 2 + 1] = x * w01 + y * w11 + z * w21;
            }
        }
    }
    __syncthreads();

    // ---- 5 residual blocks ----
    for (int blk = 0; blk < NBLK; blk++) {
        const unsigned char* bb = g_wblob + (size_t)blk * BLK_STRIDE;
        const float* cum = g_cum + blk * 256;
        const float* b0L = b0g + blk * 256;

        // (a) netA += c @ Wc
        gemm_tf32<8>(accN, fa, SFW, (const uint4*)(bb + L0OFF), wM, wN, lane);

        // (b) tmp = relu(netA + cum) @ W0
        __syncthreads();
        epi_write(accN, cum, na, wM, wN, lane);
        __syncthreads();
        float accT[2][8][4];
#pragma unroll
        for (int mt = 0; mt < 2; mt++)
#pragma unroll
            for (int nt = 0; nt < 8; nt++)
#pragma unroll
                for (int r4 = 0; r4 < 4; r4++) accT[mt][nt][r4] = 0.0f;
        gemm_tf32<16>(accT, na, SNW, (const uint4*)(bb + L1OFF), wM, wN, lane);

        // (c) netA += relu(tmp + b0) @ W1
        __syncthreads();
        epi_write(accT, b0L, na, wM, wN, lane);
        __syncthreads();
        gemm_tf32<16>(accN, na, SNW, (const uint4*)(bb + L2OFF), wM, wN, lane);
    }

    // ---- output: out = relu(netA + cumF) @ Wout + bout ----
    {
        const float* cumF = g_cum + NBLK * 256;
        float part[2][2] = {{0.f, 0.f}, {0.f, 0.f}};
#pragma unroll
        for (int mt = 0; mt < 2; mt++)
#pragma unroll
            for (int nt = 0; nt < 8; nt++) {
                int C = wN * 64 + nt * 8 + (lane & 3) * 2;
                float c0 = __ldg(cumF + C), c1 = __ldg(cumF + C + 1);
                float w0 = __ldg(Wout + C), w1 = __ldg(Wout + C + 1);
#pragma unroll
                for (int rh = 0; rh < 2; rh++) {
                    part[mt][rh] += fmaxf(accN[mt][nt][rh * 2 + 0] + c0, 0.0f) * w0
                                  + fmaxf(accN[mt][nt][rh * 2 + 1] + c1, 0.0f) * w1;
                }
            }
#pragma unroll
        for (int mt = 0; mt < 2; mt++)
#pragma unroll
            for (int rh = 0; rh < 2; rh++) {
                float v = part[mt][rh];
                v += __shfl_xor_sync(0xFFFFFFFFu, v, 1);
                v += __shfl_xor_sync(0xFFFFFFFFu, v, 2);
                if ((lane & 3) == 0) {
                    int R = wM * 32 + mt * 16 + (lane >> 2) + rh * 8;
                    s.outp[R][wN] = v;
                }
            }
        __syncthreads();
        if (tid < MT) {
            float v = s.outp[tid][0] + s.outp[tid][1] + s.outp[tid][2] + s.outp[tid][3]
                    + __ldg(bout);
            out[q0 + tid] = v;
        }
    }
}

extern "C" void kernel_launch(void* const* d_in, const int* in_sizes, int n_in,
                              void* d_out, int out_size) {
    const float* p      = (const float*)d_in[0];
    const float* c_grid = (const float*)d_in[1];
    const float* c_xy   = (const float*)d_in[2];
    const float* c_yz   = (const float*)d_in[3];
    const float* c_xz   = (const float*)d_in[4];
    const float* Wp     = (const float*)d_in[5];
    const float* bp     = (const float*)d_in[6];
    const float* Wc     = (const float*)d_in[7];
    const float* bc     = (const float*)d_in[8];
    const float* W0     = (const float*)d_in[9];
    const float* b0     = (const float*)d_in[10];
    const float* W1     = (const float*)d_in[11];
    const float* b1     = (const float*)d_in[12];
    const float* Wout   = (const float*)d_in[13];
    const float* bout   = (const float*)d_in[14];
    float* out = (float*)d_out;

    int smem = (int)sizeof(SMX);
    cudaFuncSetAttribute(decoder_kernel,
                         cudaFuncAttributeMaxDynamicSharedMemorySize, smem);

    prep_kernel<<<256, 256>>>(Wc, W0, W1, bp, bc, b1);
    decoder_kernel<<<NBLOCKS, THREADS, smem>>>(
        p, c_grid, c_xy, c_yz, c_xz, Wp, b0, Wout, bout, out);
}